// round 11
// baseline (speedup 1.0000x reference)
#include <cuda_runtime.h>

// out[b,i,d] = x[b,i] * W[i,d] + b[i,d]
// B=128, N=1024, D=512 fp32. Pure HBM-write-bound: 268MB out, 4.5MB in.
//
// R8 = R5 structure (B_PER_BLOCK=16, smem-staged x, __stcs streaming
// stores, regs<=40) made PERSISTENT: grid = 148 SMs x 8 CTAs = 1184 (one
// exact wave), each CTA grid-strides over the 8192 (i, bc) tiles. The
// store queue never drains between waves -- next tile's W/b/x loads are
// independent of the previous tile's in-flight stores and pipeline into
// the gaps. Occupancy/waves/unroll levers are exhausted (R2/R3/R6/R7);
// this targets the remaining ~30% DRAM idle directly.

#define BB 128
#define NN 1024
#define DD 512
#define D4 (DD / 4)            // 128 float4 per row == blockDim
#define B_PER_BLOCK 16
#define N_CHUNKS (BB / B_PER_BLOCK)      // 8
#define N_TILES  (NN * N_CHUNKS)         // 8192
#define GRID_P   (148 * 8)               // 1184 = one full wave

__global__ __launch_bounds__(D4, 8)
void fused_scalar_linear_kernel(const float* __restrict__ x,
                                const float4* __restrict__ W,
                                const float4* __restrict__ bias,
                                float4* __restrict__ out) {
    __shared__ float xs[B_PER_BLOCK];

    const int d4 = threadIdx.x;    // 0..D4-1

    for (int t = blockIdx.x; t < N_TILES; t += GRID_P) {
        const int i  = t >> 3;           // neuron row 0..NN-1
        const int bc = t & (N_CHUNKS - 1);
        const int b0 = bc * B_PER_BLOCK;

        __syncthreads();   // all warps done reading xs from previous tile

        // One LDG for the whole CTA: lanes 0-15 of warp 0 fetch the chunk's
        // 16 x scalars (stride NN) into smem.
        if (d4 < B_PER_BLOCK) {
            xs[d4] = __ldg(&x[(size_t)(b0 + d4) * NN + i]);
        }

        // Per-tile register load of this thread's W/b slice (L2-resident).
        const float4 w  = W[i * D4 + d4];
        const float4 bv = bias[i * D4 + d4];

        __syncthreads();

        float4* __restrict__ o_base = out + (size_t)i * D4 + d4;

        #pragma unroll
        for (int k = 0; k < B_PER_BLOCK; ++k) {
            const float xv = xs[k];      // conflict-free LDS broadcast
            float4 o;
            o.x = fmaf(xv, w.x, bv.x);
            o.y = fmaf(xv, w.y, bv.y);
            o.z = fmaf(xv, w.z, bv.z);
            o.w = fmaf(xv, w.w, bv.w);
            // Streaming (evict-first) store: 2KB contiguous per CTA row.
            __stcs(o_base + (size_t)(b0 + k) * (NN * D4), o);
        }
    }
}

extern "C" void kernel_launch(void* const* d_in, const int* in_sizes, int n_in,
                              void* d_out, int out_size) {
    const float*  x    = (const float*)d_in[0];   // [B, N, 1]
    const float4* W    = (const float4*)d_in[1];  // [N, D]
    const float4* bias = (const float4*)d_in[2];  // [N, D]
    float4* out = (float4*)d_out;                 // [B, N, D]

    fused_scalar_linear_kernel<<<GRID_P, D4>>>(x, W, bias, out);
}

// round 13
// speedup vs baseline: 1.0447x; 1.0447x over previous
#include <cuda_runtime.h>

// out[b,i,d] = x[b,i] * W[i,d] + b[i,d]
// B=128, N=1024, D=512 fp32. Pure HBM-write-bound: 268MB out, 4.5MB in.
//
// R9 = R5 config (grid 8192, B_PER_BLOCK=16, smem-staged x, streaming
// stores) with Blackwell 256-bit stores (st.global.cs.v8.f32 -> STG.256).
// 128 threads = 2 half-teams of 64; each thread owns 8 consecutive floats
// of the D=512 row, stores 8x STG.256 instead of 16x STG.128. Halves
// store-issue + L1tex dispatch work per byte; per-warp store burst is
// 32 lanes x 32B = 1KB contiguous. Sustained rate is at the HBM write
// floor (~6.5TB/s across replays); this targets issue-path efficiency.

#define BB 128
#define NN 1024
#define DD 512
#define D8 (DD / 8)            // 64 8-float slices per row
#define B_PER_BLOCK 16

__global__ __launch_bounds__(128, 8)
void fused_scalar_linear_kernel(const float* __restrict__ x,
                                const float* __restrict__ W,
                                const float* __restrict__ bias,
                                float* __restrict__ out) {
    __shared__ float xs[B_PER_BLOCK];

    const int i    = blockIdx.x;           // neuron row 0..NN-1
    const int bc   = blockIdx.y;           // batch chunk 0..7
    const int t    = threadIdx.x;          // 0..127
    const int half = t >> 6;               // 0/1: which batch parity this thread serves
    const int c8   = t & 63;               // 8-float slice index within the row
    const int b0   = bc * B_PER_BLOCK;

    // One LDG instruction for the whole CTA: lanes 0-15 of warp 0 fetch the
    // chunk's 16 x scalars (stride NN) into smem.
    if (t < B_PER_BLOCK) {
        xs[t] = __ldg(&x[(size_t)(b0 + t) * NN + i]);
    }

    // One-time register load of this thread's 8-float W/b slice (32B, aligned).
    const float4* Wp = (const float4*)(W    + (size_t)i * DD + c8 * 8);
    const float4* Bp = (const float4*)(bias + (size_t)i * DD + c8 * 8);
    const float4 w0 = Wp[0], w1 = Wp[1];
    const float4 v0 = Bp[0], v1 = Bp[1];

    __syncthreads();

    // Base address of this thread's 32B output slice in row i.
    float* o_base = out + (size_t)i * DD + c8 * 8;

    #pragma unroll
    for (int j = 0; j < B_PER_BLOCK / 2; ++j) {
        const int k = (j << 1) | half;     // this thread's batch for iter j
        const float xv = xs[k];            // conflict-free LDS broadcast

        float o0 = fmaf(xv, w0.x, v0.x);
        float o1 = fmaf(xv, w0.y, v0.y);
        float o2 = fmaf(xv, w0.z, v0.z);
        float o3 = fmaf(xv, w0.w, v0.w);
        float o4 = fmaf(xv, w1.x, v1.x);
        float o5 = fmaf(xv, w1.y, v1.y);
        float o6 = fmaf(xv, w1.z, v1.z);
        float o7 = fmaf(xv, w1.w, v1.w);

        float* addr = o_base + (size_t)(b0 + k) * (NN * DD);
        // Blackwell 256-bit streaming store (STG.256, evict-first).
        asm volatile(
            "st.global.cs.v8.f32 [%0], {%1, %2, %3, %4, %5, %6, %7, %8};"
            :: "l"(addr),
               "f"(o0), "f"(o1), "f"(o2), "f"(o3),
               "f"(o4), "f"(o5), "f"(o6), "f"(o7)
            : "memory");
    }
}

extern "C" void kernel_launch(void* const* d_in, const int* in_sizes, int n_in,
                              void* d_out, int out_size) {
    const float* x    = (const float*)d_in[0];   // [B, N, 1]
    const float* W    = (const float*)d_in[1];   // [N, D]
    const float* bias = (const float*)d_in[2];   // [N, D]
    float* out = (float*)d_out;                  // [B, N, D]

    dim3 grid(NN, BB / B_PER_BLOCK);
    fused_scalar_linear_kernel<<<grid, 128>>>(x, W, bias, out);
}

// round 16
// speedup vs baseline: 1.1481x; 1.0990x over previous
#include <cuda_runtime.h>

// out[b,i,d] = x[b,i] * W[i,d] + b[i,d]
// B=128, N=1024, D=512 fp32. Pure HBM-write-bound: 268MB out, 4.5MB in.
//
// R10 = R5 (best: grid 8192, B_PER_BLOCK=16, __stcs streaming stores) with
// the smem x-stage replaced by per-warp shuffle broadcast. R5 made warps
// 1-3 wait at __syncthreads for warp 0's x LDG -- a full load-latency
// bubble in front of every CTA's store stream. Now each warp loads the 16
// x scalars itself (lanes 0-15, one LDG; L1-hit after first warp) and
// broadcasts via __shfl_sync: no smem, no barrier, warps fully decoupled.

#define BB 128
#define NN 1024
#define DD 512
#define D4 (DD / 4)          // 128 float4 per row == blockDim
#define B_PER_BLOCK 16

__global__ __launch_bounds__(D4, 8)
void fused_scalar_linear_kernel(const float* __restrict__ x,
                                const float4* __restrict__ W,
                                const float4* __restrict__ bias,
                                float4* __restrict__ out) {
    const int i    = blockIdx.x;         // neuron row 0..NN-1
    const int bc   = blockIdx.y;         // batch chunk 0..BB/B_PER_BLOCK-1
    const int d4   = threadIdx.x;        // 0..D4-1
    const int lane = d4 & 31;
    const int b0   = bc * B_PER_BLOCK;

    // Each warp fetches the chunk's 16 x scalars itself (lanes 0-15, one
    // LDG; stride NN). No cross-warp dependency, no barrier.
    float xval = 0.0f;
    if (lane < B_PER_BLOCK) {
        xval = __ldg(&x[(size_t)(b0 + lane) * NN + i]);
    }

    // One-time register load of this thread's W/b slice.
    const float4 w  = W[i * D4 + d4];
    const float4 bv = bias[i * D4 + d4];

    float4* __restrict__ o_base = out + (size_t)i * D4 + d4;

    #pragma unroll
    for (int k = 0; k < B_PER_BLOCK; ++k) {
        const float xv = __shfl_sync(0xffffffffu, xval, k);  // warp broadcast
        float4 o;
        o.x = fmaf(xv, w.x, bv.x);
        o.y = fmaf(xv, w.y, bv.y);
        o.z = fmaf(xv, w.z, bv.z);
        o.w = fmaf(xv, w.w, bv.w);
        // Streaming (evict-first) store: 2KB contiguous per CTA row.
        __stcs(o_base + (size_t)(b0 + k) * (NN * D4), o);
    }
}

extern "C" void kernel_launch(void* const* d_in, const int* in_sizes, int n_in,
                              void* d_out, int out_size) {
    const float*  x    = (const float*)d_in[0];   // [B, N, 1]
    const float4* W    = (const float4*)d_in[1];  // [N, D]
    const float4* bias = (const float4*)d_in[2];  // [N, D]
    float4* out = (float4*)d_out;                 // [B, N, D]

    dim3 grid(NN, BB / B_PER_BLOCK);
    fused_scalar_linear_kernel<<<grid, D4>>>(x, W, bias, out);
}